// round 4
// baseline (speedup 1.0000x reference)
#include <cuda_runtime.h>
#include <math.h>
#include <stdint.h>

#define TT     2048
#define HIDD   5120
#define QLRD   1536
#define ROPED  64
#define NOPED  128
#define HH     32
#define QKDD   192
#define DQK    576
#define DLAT   512
#define QBN    6144   // H*QKD
#define ATTN   4096   // H*VDIM
#define SCALE_F 0.07216878364870323f   // 1/sqrt(192)  (QKD = NOPE+ROPE = 192)
#define EPS_F  1e-6f

// ----------------------------- scratch ---------------------------------------
__device__ float g_qa    [(size_t)TT * QLRD];        // 12.6 MB
__device__ float g_q     [(size_t)TT * QBN];         // 50 MB
__device__ float g_lat   [(size_t)TT * DQK];         // 4.7 MB
__device__ float g_k     [(size_t)TT * DQK];         // 4.7 MB  [v_norm(512) | k_pe_rope(64)]
__device__ float g_kT    [(size_t)DQK * TT];         // 4.7 MB
__device__ float g_qin   [(size_t)TT * HH * DQK];    // 151 MB
__device__ float g_scores[(size_t)HH * TT * TT];     // 537 MB
__device__ float g_ctx   [(size_t)HH * TT * DLAT];   // 134 MB
__device__ float g_att   [(size_t)TT * ATTN];        // 33.5 MB

// ------------------------ generic tiled SGEMM --------------------------------
// C[M,N] = A[M,K]*B[K,N], row-major w/ leading dims; batched over blockIdx.z.
// 128x128 tile, BK=16, 256 thr, 8x8/thread. Requires M%128==0, K%16==0, N%4==0.
__global__ __launch_bounds__(256, 2)
void sgemm(const float* __restrict__ A, const float* __restrict__ B, float* __restrict__ C,
           int M, int N, int K, int lda, int ldb, int ldc,
           long long sA, long long sB, long long sC)
{
    A += (long long)blockIdx.z * sA;
    B += (long long)blockIdx.z * sB;
    C += (long long)blockIdx.z * sC;

    __shared__ float As[16][132];
    __shared__ float Bs[16][132];

    const int tid = threadIdx.x;
    const int tx = tid & 15, ty = tid >> 4;
    const int bm = blockIdx.y * 128, bn = blockIdx.x * 128;

    float acc[8][8];
#pragma unroll
    for (int i = 0; i < 8; i++)
#pragma unroll
        for (int j = 0; j < 8; j++) acc[i][j] = 0.f;

    for (int k0 = 0; k0 < K; k0 += 16) {
#pragma unroll
        for (int it = 0; it < 2; it++) {
            int idx  = tid + it * 256;
            int arow = idx >> 2;
            int ak   = (idx & 3) << 2;
            float4 v = *(const float4*)&A[(size_t)(bm + arow) * lda + k0 + ak];
            As[ak + 0][arow] = v.x; As[ak + 1][arow] = v.y;
            As[ak + 2][arow] = v.z; As[ak + 3][arow] = v.w;
        }
#pragma unroll
        for (int it = 0; it < 2; it++) {
            int idx  = tid + it * 256;
            int bk   = idx >> 5;
            int bcol = (idx & 31) << 2;
            float4 v = make_float4(0.f, 0.f, 0.f, 0.f);
            if (bn + bcol < N)
                v = *(const float4*)&B[(size_t)(k0 + bk) * ldb + bn + bcol];
            *(float4*)&Bs[bk][bcol] = v;
        }
        __syncthreads();

#pragma unroll
        for (int kk = 0; kk < 16; kk++) {
            float a[8], b[8];
            *(float4*)&a[0] = *(const float4*)&As[kk][ty * 4];
            *(float4*)&a[4] = *(const float4*)&As[kk][64 + ty * 4];
            *(float4*)&b[0] = *(const float4*)&Bs[kk][tx * 4];
            *(float4*)&b[4] = *(const float4*)&Bs[kk][64 + tx * 4];
#pragma unroll
            for (int i = 0; i < 8; i++)
#pragma unroll
                for (int j = 0; j < 8; j++)
                    acc[i][j] += a[i] * b[j];
        }
        __syncthreads();
    }

#pragma unroll
    for (int i = 0; i < 8; i++) {
        int r = bm + ((i >> 2) << 6) + ty * 4 + (i & 3);
#pragma unroll
        for (int j = 0; j < 8; j++) {
            int c = bn + ((j >> 2) << 6) + tx * 4 + (j & 3);
            if (c < N) C[(size_t)r * ldc + c] = acc[i][j];
        }
    }
}

// ------------------------- block reduce helper -------------------------------
__device__ __forceinline__ float blockReduce(float v, bool isMax)
{
    __shared__ float sm[9];
    int lane = threadIdx.x & 31, w = threadIdx.x >> 5;
#pragma unroll
    for (int o = 16; o > 0; o >>= 1) {
        float ov = __shfl_xor_sync(0xffffffffu, v, o);
        v = isMax ? fmaxf(v, ov) : v + ov;
    }
    if (lane == 0) sm[w] = v;
    __syncthreads();
    if (w == 0) {
        int nw = blockDim.x >> 5;
        v = (lane < nw) ? sm[lane] : (isMax ? -INFINITY : 0.f);
#pragma unroll
        for (int o = 4; o > 0; o >>= 1) {
            float ov = __shfl_xor_sync(0xffffffffu, v, o);
            v = isMax ? fmaxf(v, ov) : v + ov;
        }
        if (lane == 0) sm[8] = v;
    }
    __syncthreads();
    return sm[8];
}

// ----------------------------- rmsnorm rows ----------------------------------
__global__ void rmsnorm_rows(float* __restrict__ x, const float* __restrict__ w, int n)
{
    float* row = x + (size_t)blockIdx.x * n;
    float s = 0.f;
    for (int i = threadIdx.x; i < n; i += blockDim.x) { float v = row[i]; s += v * v; }
    s = blockReduce(s, false);
    float sc = rsqrtf(s / (float)n + EPS_F);
    for (int i = threadIdx.x; i < n; i += blockDim.x) row[i] = row[i] * sc * w[i];
}

// ---- rope helper: position == row index t (reference: positions=arange(T)) ---
// fp32 phase to match reference, double range-reduction for accurate sin/cos.
__device__ __forceinline__ void rope_cs(int posv, int j, float& c, float& s)
{
    float e    = (float)(2 * j) * (1.0f / 64.0f);
    float invf = 1.0f / powf(10000.0f, e);
    float freq = (float)posv * invf;              // fp32 phase, matches reference
    double fd  = (double)freq;
    double q   = floor(fd * 0.15915494309189535); // 1/(2*pi)
    double r   = fd - q * 6.283185307179586;
    float  rf  = (float)r;
    c = cosf(rf);
    s = sinf(rf);
}

// ------------------- build k_input: rmsnorm(512) + rope(64) ------------------
__global__ void build_k(const float* __restrict__ lat, const float* __restrict__ w,
                        float* __restrict__ k)
{
    int t = blockIdx.x;
    const float* L = lat + (size_t)t * DQK;
    float*       K = k   + (size_t)t * DQK;

    float ssq = 0.f;
    for (int i = threadIdx.x; i < DLAT; i += blockDim.x) { float v = L[i]; ssq += v * v; }
    ssq = blockReduce(ssq, false);
    float sc = rsqrtf(ssq / (float)DLAT + EPS_F);
    for (int i = threadIdx.x; i < DLAT; i += blockDim.x) K[i] = L[i] * sc * w[i];

    if (threadIdx.x < 32) {
        int j = threadIdx.x;
        float c, s;
        rope_cs(t, j, c, s);
        float x1 = L[DLAT + 2 * j], x2 = L[DLAT + 2 * j + 1];
        K[DLAT + 2 * j]     = x1 * c - x2 * s;
        K[DLAT + 2 * j + 1] = x2 * c + x1 * s;
    }
}

// --------------------------- q-side rope -> qin ------------------------------
__global__ void rope_q(const float* __restrict__ q, float* __restrict__ qin)
{
    int t = blockIdx.x, h = blockIdx.y, j = threadIdx.x;  // 32 threads
    const float* src = q   + (size_t)t * QBN + h * QKDD + NOPED;
    float*       dst = qin + ((size_t)t * HH + h) * DQK + DLAT;
    float c, s;
    rope_cs(t, j, c, s);
    float x1 = src[2 * j], x2 = src[2 * j + 1];
    dst[2 * j]     = x1 * c - x2 * s;
    dst[2 * j + 1] = x2 * c + x1 * s;
}

// ---------------------------- k transpose ------------------------------------
__global__ void transpose_k(const float* __restrict__ in, float* __restrict__ out)
{
    __shared__ float tile[32][33];
    int x = blockIdx.x * 32 + threadIdx.x;   // col in input (0..575)
    int y = blockIdx.y * 32 + threadIdx.y;   // row in input
#pragma unroll
    for (int i = 0; i < 32; i += 8)
        tile[threadIdx.y + i][threadIdx.x] = in[(size_t)(y + i) * DQK + x];
    __syncthreads();
    int xo = blockIdx.y * 32 + threadIdx.x;  // col in output
    int yo = blockIdx.x * 32 + threadIdx.y;  // row in output
#pragma unroll
    for (int i = 0; i < 32; i += 8)
        out[(size_t)(yo + i) * TT + xo] = tile[threadIdx.x][threadIdx.y + i];
}

// ------------------------- causal softmax (in place) -------------------------
__global__ void softmax_causal(float* __restrict__ scores)
{
    int t = blockIdx.x, h = blockIdx.y;
    float* row = scores + ((size_t)h * TT + t) * TT;
    int n = t + 1;

    float m = -INFINITY;
    for (int i = threadIdx.x; i < n; i += blockDim.x)
        m = fmaxf(m, row[i] * SCALE_F);
    m = blockReduce(m, true);

    float s = 0.f;
    for (int i = threadIdx.x; i < n; i += blockDim.x)
        s += expf(row[i] * SCALE_F - m);
    s = blockReduce(s, false);
    float inv = 1.f / s;

    for (int i = threadIdx.x; i < TT; i += blockDim.x)
        row[i] = (i < n) ? expf(row[i] * SCALE_F - m) * inv : 0.f;
}

// ------------------------------- launch --------------------------------------
extern "C" void kernel_launch(void* const* d_in, const int* in_sizes, int n_in,
                              void* d_out, int out_size)
{
    const float*     hs       = (const float*)d_in[0];
    // d_in[1] (positions) == arange(T); row index is used directly (dtype-proof)
    const float*     w_q_a    = (const float*)d_in[2];
    const float*     q_a_ln_w = (const float*)d_in[3];
    const float*     w_q_b    = (const float*)d_in[4];
    const float*     w_kv_a   = (const float*)d_in[5];
    const float*     kv_ln_w  = (const float*)d_in[6];
    const float*     w_kc     = (const float*)d_in[7];
    const float*     w_vc     = (const float*)d_in[8];
    const float*     w_o      = (const float*)d_in[9];
    float*           out      = (float*)d_out;

    float *p_qa, *p_q, *p_lat, *p_k, *p_kT, *p_qin, *p_sc, *p_ctx, *p_att;
    cudaGetSymbolAddress((void**)&p_qa,  g_qa);
    cudaGetSymbolAddress((void**)&p_q,   g_q);
    cudaGetSymbolAddress((void**)&p_lat, g_lat);
    cudaGetSymbolAddress((void**)&p_k,   g_k);
    cudaGetSymbolAddress((void**)&p_kT,  g_kT);
    cudaGetSymbolAddress((void**)&p_qin, g_qin);
    cudaGetSymbolAddress((void**)&p_sc,  g_scores);
    cudaGetSymbolAddress((void**)&p_ctx, g_ctx);
    cudaGetSymbolAddress((void**)&p_att, g_att);

    const int MB = TT / 128;  // 16

    // 1) qa = hidden @ w_q_a                        (2048,5120)x(5120,1536)
    sgemm<<<dim3(QLRD / 128, MB, 1), 256>>>(hs, w_q_a, p_qa,
        TT, QLRD, HIDD, HIDD, QLRD, QLRD, 0, 0, 0);
    // 2) rmsnorm rows of qa
    rmsnorm_rows<<<TT, 256>>>(p_qa, q_a_ln_w, QLRD);
    // 3) q = qa @ w_q_b                             (2048,1536)x(1536,6144)
    sgemm<<<dim3(QBN / 128, MB, 1), 256>>>(p_qa, w_q_b, p_q,
        TT, QBN, QLRD, QLRD, QBN, QBN, 0, 0, 0);
    // 4) latent = hidden @ w_kv_a                   (2048,5120)x(5120,576)
    sgemm<<<dim3((DQK + 127) / 128, MB, 1), 256>>>(hs, w_kv_a, p_lat,
        TT, DQK, HIDD, HIDD, DQK, DQK, 0, 0, 0);
    // 5) k_input = [rmsnorm(latent[:,:512]) | rope(latent[:,512:])]
    build_k<<<TT, 256>>>(p_lat, kv_ln_w, p_k);
    // 6) kT
    transpose_k<<<dim3(DQK / 32, TT / 32), dim3(32, 8)>>>(p_k, p_kT);
    // 7) qin[:, :512] per head = q_nope @ w_kc[h]   batched z=32
    sgemm<<<dim3(DLAT / 128, MB, HH), 256>>>(p_q, w_kc, p_qin,
        TT, DLAT, NOPED, QBN, DLAT, HH * DQK,
        (long long)QKDD, (long long)NOPED * DLAT, (long long)DQK);
    // 8) qin[:, 512:] = rope(q_pe)
    rope_q<<<dim3(TT, HH), 32>>>(p_q, p_qin);
    // 9) scores[h] = qin[h] @ kT                    batched z=32
    sgemm<<<dim3(MB, MB, HH), 256>>>(p_qin, p_kT, p_sc,
        TT, TT, DQK, HH * DQK, TT, TT,
        (long long)DQK, 0LL, (long long)TT * TT);
    // 10) causal softmax in place
    softmax_causal<<<dim3(TT, HH), 256>>>(p_sc);
    // 11) ctx[h] = probs[h] @ v_input               batched z=32 (B shared)
    sgemm<<<dim3(DLAT / 128, MB, HH), 256>>>(p_sc, p_k, p_ctx,
        TT, DLAT, TT, TT, DQK, DLAT,
        (long long)TT * TT, 0LL, (long long)TT * DLAT);
    // 12) att[:, h*128:(h+1)*128] = ctx[h] @ w_vc[h] batched z=32
    sgemm<<<dim3(1, MB, HH), 256>>>(p_ctx, w_vc, p_att,
        TT, NOPED, DLAT, DLAT, NOPED, ATTN,
        (long long)TT * DLAT, (long long)DLAT * NOPED, (long long)NOPED);
    // 13) out = att @ w_o                           (2048,4096)x(4096,5120)
    sgemm<<<dim3(HIDD / 128, MB, 1), 256>>>(p_att, w_o, out,
        TT, HIDD, ATTN, ATTN, HIDD, HIDD, 0, 0, 0);
}

// round 9
// speedup vs baseline: 2.6873x; 2.6873x over previous
#include <cuda_runtime.h>
#include <cuda_bf16.h>
#include <math.h>
#include <stdint.h>

#define TT     2048
#define HIDD   5120
#define ROPED  64
#define NOPED  128
#define HH     32
#define QKDD   192
#define QLRD   1536
#define DQK    576
#define DLAT   512
#define QBN    6144   // H*QKD
#define ATTN   4096   // H*VDIM
#define SCALE_F 0.07216878364870323f   // 1/sqrt(192)
#define EPS_F  1e-6f

typedef __nv_bfloat16 bf16;

// ----------------------------- f32 scratch -----------------------------------
__device__ float g_qa    [(size_t)TT * QLRD];
__device__ float g_q     [(size_t)TT * QBN];
__device__ float g_lat   [(size_t)TT * DQK];
__device__ float g_k     [(size_t)TT * DQK];
__device__ float g_qin   [(size_t)TT * HH * DQK];
__device__ float g_scores[(size_t)HH * TT * TT];
__device__ float g_ctx   [(size_t)HH * TT * DLAT];
__device__ float g_att   [(size_t)TT * ATTN];

// --------------------------- bf16 hi/lo scratch -------------------------------
__device__ bf16 g_hsH [(size_t)TT*HIDD],      g_hsL [(size_t)TT*HIDD];
__device__ bf16 g_wqaT_H[(size_t)QLRD*HIDD],  g_wqaT_L[(size_t)QLRD*HIDD];
__device__ bf16 g_qaH [(size_t)TT*QLRD],      g_qaL [(size_t)TT*QLRD];
__device__ bf16 g_wqbT_H[(size_t)QBN*QLRD],   g_wqbT_L[(size_t)QBN*QLRD];
__device__ bf16 g_qH  [(size_t)TT*QBN],       g_qL  [(size_t)TT*QBN];
__device__ bf16 g_wkvaT_H[(size_t)640*HIDD],  g_wkvaT_L[(size_t)640*HIDD];   // padded 576->640
__device__ bf16 g_kH  [(size_t)TT*DQK],       g_kL  [(size_t)TT*DQK];
__device__ bf16 g_vT_H[(size_t)DLAT*TT],      g_vT_L[(size_t)DLAT*TT];
__device__ bf16 g_wkcT_H[(size_t)HH*DLAT*NOPED], g_wkcT_L[(size_t)HH*DLAT*NOPED];
__device__ bf16 g_qinH[(size_t)TT*HH*DQK],    g_qinL[(size_t)TT*HH*DQK];
__device__ bf16 g_scH [(size_t)HH*TT*TT],     g_scL [(size_t)HH*TT*TT];
__device__ bf16 g_ctxH[(size_t)HH*TT*DLAT],   g_ctxL[(size_t)HH*TT*DLAT];
__device__ bf16 g_wvcT_H[(size_t)HH*NOPED*DLAT], g_wvcT_L[(size_t)HH*NOPED*DLAT];
__device__ bf16 g_attH[(size_t)TT*ATTN],      g_attL[(size_t)TT*ATTN];
__device__ bf16 g_woT_H[(size_t)HIDD*ATTN],   g_woT_L[(size_t)HIDD*ATTN];

// ------------------------------ helpers ---------------------------------------
__device__ __forceinline__ uint32_t smem_u32(const void* p) {
    uint32_t a;
    asm("{ .reg .u64 t; cvta.to.shared.u64 t, %1; cvt.u32.u64 %0, t; }" : "=r"(a) : "l"(p));
    return a;
}

#define SWZ(o) ((o) ^ (((o) >> 3) & 0x70))

__device__ __forceinline__ void ldm_x4(uint32_t* r, uint32_t addr) {
    asm volatile("ldmatrix.sync.aligned.m8n8.x4.shared.b16 {%0,%1,%2,%3}, [%4];"
        : "=r"(r[0]), "=r"(r[1]), "=r"(r[2]), "=r"(r[3]) : "r"(addr));
}

__device__ __forceinline__ void mma16816(float* c, const uint32_t* a, const uint32_t* b) {
    asm volatile("mma.sync.aligned.m16n8k16.row.col.f32.bf16.bf16.f32 "
        "{%0,%1,%2,%3}, {%4,%5,%6,%7}, {%8,%9}, {%0,%1,%2,%3};"
        : "+f"(c[0]), "+f"(c[1]), "+f"(c[2]), "+f"(c[3])
        : "r"(a[0]), "r"(a[1]), "r"(a[2]), "r"(a[3]), "r"(b[0]), "r"(b[1]));
}

// ----------------------- warp-MMA 3-term split GEMM ---------------------------
// C[M,N] = A[M,K] * BT[N,K]^T, fp32 C; A/BT given as bf16 hi/lo pairs (K-contig).
// 128x128 CTA tile, K-chunks of 64. mode: 0 none, 1 causal-skip, 2 k-limit (pv)
#define GSM_A_HI 0
#define GSM_A_LO 16384
#define GSM_B_HI 32768
#define GSM_B_LO 49152
#define GSM_DYN  (65536 + 1024)

__global__ __launch_bounds__(256, 2)
void gemm3(const bf16* __restrict__ AH, const bf16* __restrict__ AL,
           const bf16* __restrict__ BH, const bf16* __restrict__ BL,
           float* __restrict__ C, int N, int K, int lda, int ldb, int ldc,
           long long sA, long long sB, long long sC, int mode)
{
    const int bm = blockIdx.y * 128, bn = blockIdx.x * 128;
    if (mode == 1 && bn >= bm + 128) return;
    const int kmax = (mode == 2) ? (bm + 128) : K;

    AH += (long long)blockIdx.z * sA;  AL += (long long)blockIdx.z * sA;
    BH += (long long)blockIdx.z * sB;  BL += (long long)blockIdx.z * sB;
    C  += (long long)blockIdx.z * sC;

    extern __shared__ char smraw[];
    char* smem = (char*)(((uintptr_t)smraw + 1023) & ~(uintptr_t)1023);
    const uint32_t sb = smem_u32(smem);

    const int tid  = threadIdx.x;
    const int lane = tid & 31, warp = tid >> 5;
    const int wm = (warp >> 2) * 64;     // warp M offset within tile
    const int wn = (warp & 3) * 32;      // warp N offset within tile

    float acc[4][4][4];
#pragma unroll
    for (int i = 0; i < 4; i++)
#pragma unroll
        for (int j = 0; j < 4; j++)
#pragma unroll
            for (int q = 0; q < 4; q++) acc[i][j][q] = 0.f;

    const int a_row = (lane & 15);
    const int a_kof = (lane & 16) ? 8 : 0;
    const int b_sel = lane >> 3;
    const int b_row = (lane & 7) + ((b_sel & 2) ? 8 : 0);
    const int b_kof = (b_sel & 1) ? 8 : 0;

    for (int k0 = 0; k0 < kmax; k0 += 64) {
#pragma unroll
        for (int it = 0; it < 4; it++) {
            int idx = tid + it * 256;
            int row = idx >> 3, c16 = idx & 7;
            uint32_t sw = SWZ((uint32_t)(row * 128 + c16 * 16));
            size_t gA = (size_t)(bm + row) * lda + k0 + c16 * 8;
            size_t gB = (size_t)(bn + row) * ldb + k0 + c16 * 8;
            *(float4*)(smem + GSM_A_HI + sw) = *(const float4*)(AH + gA);
            *(float4*)(smem + GSM_A_LO + sw) = *(const float4*)(AL + gA);
            *(float4*)(smem + GSM_B_HI + sw) = *(const float4*)(BH + gB);
            *(float4*)(smem + GSM_B_LO + sw) = *(const float4*)(BL + gB);
        }
        __syncthreads();

#pragma unroll
        for (int kk = 0; kk < 64; kk += 16) {
            uint32_t bh[4][2], bl[4][2];
#pragma unroll
            for (int p = 0; p < 2; p++) {
                uint32_t boff = SWZ((uint32_t)((wn + p * 16 + b_row) * 128 + (kk + b_kof) * 2));
                uint32_t r[4];
                ldm_x4(r, sb + GSM_B_HI + boff);
                bh[2*p][0] = r[0]; bh[2*p][1] = r[1]; bh[2*p+1][0] = r[2]; bh[2*p+1][1] = r[3];
                ldm_x4(r, sb + GSM_B_LO + boff);
                bl[2*p][0] = r[0]; bl[2*p][1] = r[1]; bl[2*p+1][0] = r[2]; bl[2*p+1][1] = r[3];
            }
#pragma unroll
            for (int mt = 0; mt < 4; mt++) {
                uint32_t aoff = SWZ((uint32_t)((wm + mt * 16 + a_row) * 128 + (kk + a_kof) * 2));
                uint32_t ah[4], al[4];
                ldm_x4(ah, sb + GSM_A_HI + aoff);
                ldm_x4(al, sb + GSM_A_LO + aoff);
#pragma unroll
                for (int nt = 0; nt < 4; nt++) {
                    mma16816(acc[mt][nt], ah, bh[nt]);
                    mma16816(acc[mt][nt], ah, bl[nt]);
                    mma16816(acc[mt][nt], al, bh[nt]);
                }
            }
        }
        __syncthreads();
    }

#pragma unroll
    for (int mt = 0; mt < 4; mt++) {
#pragma unroll
        for (int nt = 0; nt < 4; nt++) {
            int r = bm + wm + mt * 16 + (lane >> 2);
            int c = bn + wn + nt * 8 + 2 * (lane & 3);
            if (c < N) {
                *(float2*)&C[(size_t)r * ldc + c]       = make_float2(acc[mt][nt][0], acc[mt][nt][1]);
                *(float2*)&C[(size_t)(r + 8) * ldc + c] = make_float2(acc[mt][nt][2], acc[mt][nt][3]);
            }
        }
    }
}

// --------------------- elementwise f32 -> bf16 hi/lo ---------------------------
__global__ void conv_split(const float* __restrict__ x, bf16* __restrict__ hi,
                           bf16* __restrict__ lo, long long n4)
{
    long long i = (long long)blockIdx.x * blockDim.x + threadIdx.x;
    long long stride = (long long)gridDim.x * blockDim.x;
    for (; i < n4; i += stride) {
        float4 v = ((const float4*)x)[i];
        bf16 hx = __float2bfloat16(v.x), hy = __float2bfloat16(v.y);
        bf16 hz = __float2bfloat16(v.z), hw = __float2bfloat16(v.w);
        float lx = v.x - __bfloat162float(hx), ly = v.y - __bfloat162float(hy);
        float lz = v.z - __bfloat162float(hz), lw = v.w - __bfloat162float(hw);
        __nv_bfloat162* H = (__nv_bfloat162*)hi;
        __nv_bfloat162* L = (__nv_bfloat162*)lo;
        H[2*i]   = __nv_bfloat162(hx, hy);
        H[2*i+1] = __nv_bfloat162(hz, hw);
        L[2*i]   = __nv_bfloat162(__float2bfloat16(lx), __float2bfloat16(ly));
        L[2*i+1] = __nv_bfloat162(__float2bfloat16(lz), __float2bfloat16(lw));
    }
}

// ------------- transpose + split: src[R][C] f32 (lda) -> dst[CP][R] bf16 -------
__global__ void tconv(const float* __restrict__ src, bf16* __restrict__ dh,
                      bf16* __restrict__ dl, int R, int C, int CP, int lda,
                      long long zs, long long zd)
{
    src += (long long)blockIdx.z * zs;
    dh  += (long long)blockIdx.z * zd;
    dl  += (long long)blockIdx.z * zd;
    __shared__ float t[32][33];
    int c  = blockIdx.x * 32 + threadIdx.x;
    int r0 = blockIdx.y * 32;
#pragma unroll
    for (int i = 0; i < 32; i += 8) {
        int r = r0 + threadIdx.y + i;
        t[threadIdx.y + i][threadIdx.x] = (c < C && r < R) ? src[(size_t)r * lda + c] : 0.f;
    }
    __syncthreads();
    int ro = blockIdx.x * 32;
    int co = r0 + threadIdx.x;
#pragma unroll
    for (int i = 0; i < 32; i += 8) {
        int rr = ro + threadIdx.y + i;
        if (rr < CP && co < R) {
            float v = t[threadIdx.x][threadIdx.y + i];   // FIXED: true transpose
            bf16 h = __float2bfloat16(v);
            dh[(size_t)rr * R + co] = h;
            dl[(size_t)rr * R + co] = __float2bfloat16(v - __bfloat162float(h));
        }
    }
}

// ------------------------- block reduce helper -------------------------------
__device__ __forceinline__ float blockReduce(float v, bool isMax)
{
    __shared__ float sm[9];
    int lane = threadIdx.x & 31, w = threadIdx.x >> 5;
#pragma unroll
    for (int o = 16; o > 0; o >>= 1) {
        float ov = __shfl_xor_sync(0xffffffffu, v, o);
        v = isMax ? fmaxf(v, ov) : v + ov;
    }
    if (lane == 0) sm[w] = v;
    __syncthreads();
    if (w == 0) {
        int nw = blockDim.x >> 5;
        v = (lane < nw) ? sm[lane] : (isMax ? -INFINITY : 0.f);
#pragma unroll
        for (int o = 4; o > 0; o >>= 1) {
            float ov = __shfl_xor_sync(0xffffffffu, v, o);
            v = isMax ? fmaxf(v, ov) : v + ov;
        }
        if (lane == 0) sm[8] = v;
    }
    __syncthreads();
    return sm[8];
}

__global__ void rmsnorm_rows(float* __restrict__ x, const float* __restrict__ w, int n)
{
    float* row = x + (size_t)blockIdx.x * n;
    float s = 0.f;
    for (int i = threadIdx.x; i < n; i += blockDim.x) { float v = row[i]; s += v * v; }
    s = blockReduce(s, false);
    float sc = rsqrtf(s / (float)n + EPS_F);
    for (int i = threadIdx.x; i < n; i += blockDim.x) row[i] = row[i] * sc * w[i];
}

__device__ __forceinline__ void rope_cs(int posv, int j, float& c, float& s)
{
    float e    = (float)(2 * j) * (1.0f / 64.0f);
    float invf = 1.0f / powf(10000.0f, e);
    float freq = (float)posv * invf;
    double fd  = (double)freq;
    double q   = floor(fd * 0.15915494309189535);
    double r   = fd - q * 6.283185307179586;
    float  rf  = (float)r;
    c = cosf(rf); s = sinf(rf);
}

__global__ void build_k(const float* __restrict__ lat, const float* __restrict__ w,
                        float* __restrict__ k)
{
    int t = blockIdx.x;
    const float* L = lat + (size_t)t * DQK;
    float*       K = k   + (size_t)t * DQK;
    float ssq = 0.f;
    for (int i = threadIdx.x; i < DLAT; i += blockDim.x) { float v = L[i]; ssq += v * v; }
    ssq = blockReduce(ssq, false);
    float sc = rsqrtf(ssq / (float)DLAT + EPS_F);
    for (int i = threadIdx.x; i < DLAT; i += blockDim.x) K[i] = L[i] * sc * w[i];
    if (threadIdx.x < 32) {
        int j = threadIdx.x;
        float c, s;
        rope_cs(t, j, c, s);
        float x1 = L[DLAT + 2*j], x2 = L[DLAT + 2*j + 1];
        K[DLAT + 2*j]     = x1 * c - x2 * s;
        K[DLAT + 2*j + 1] = x2 * c + x1 * s;
    }
}

__global__ void rope_q(const float* __restrict__ q, float* __restrict__ qin)
{
    int t = blockIdx.x, h = blockIdx.y, j = threadIdx.x;
    const float* src = q   + (size_t)t * QBN + h * QKDD + NOPED;
    float*       dst = qin + ((size_t)t * HH + h) * DQK + DLAT;
    float c, s;
    rope_cs(t, j, c, s);
    float x1 = src[2*j], x2 = src[2*j + 1];
    dst[2*j]     = x1 * c - x2 * s;
    dst[2*j + 1] = x2 * c + x1 * s;
}

__global__ void softmax_causal(float* __restrict__ scores)
{
    int t = blockIdx.x, h = blockIdx.y;
    float* row = scores + ((size_t)h * TT + t) * TT;
    int n = t + 1;
    float m = -INFINITY;
    for (int i = threadIdx.x; i < n; i += blockDim.x)
        m = fmaxf(m, row[i] * SCALE_F);
    m = blockReduce(m, true);
    float s = 0.f;
    for (int i = threadIdx.x; i < n; i += blockDim.x)
        s += expf(row[i] * SCALE_F - m);
    s = blockReduce(s, false);
    float inv = 1.f / s;
    for (int i = threadIdx.x; i < TT; i += blockDim.x)
        row[i] = (i < n) ? expf(row[i] * SCALE_F - m) * inv : 0.f;
}

// ------------------------------- launch --------------------------------------
static inline int cblk(long long n4) {
    long long b = (n4 + 255) / 256;
    return (int)(b > 262144 ? 262144 : b);
}

extern "C" void kernel_launch(void* const* d_in, const int* in_sizes, int n_in,
                              void* d_out, int out_size)
{
    const float* hs       = (const float*)d_in[0];
    const float* w_q_a    = (const float*)d_in[2];
    const float* q_a_ln_w = (const float*)d_in[3];
    const float* w_q_b    = (const float*)d_in[4];
    const float* w_kv_a   = (const float*)d_in[5];
    const float* kv_ln_w  = (const float*)d_in[6];
    const float* w_kc     = (const float*)d_in[7];
    const float* w_vc     = (const float*)d_in[8];
    const float* w_o      = (const float*)d_in[9];
    float*       out      = (float*)d_out;

    float *p_qa, *p_q, *p_lat, *p_k, *p_qin, *p_sc, *p_ctx, *p_att;
    cudaGetSymbolAddress((void**)&p_qa,  g_qa);
    cudaGetSymbolAddress((void**)&p_q,   g_q);
    cudaGetSymbolAddress((void**)&p_lat, g_lat);
    cudaGetSymbolAddress((void**)&p_k,   g_k);
    cudaGetSymbolAddress((void**)&p_qin, g_qin);
    cudaGetSymbolAddress((void**)&p_sc,  g_scores);
    cudaGetSymbolAddress((void**)&p_ctx, g_ctx);
    cudaGetSymbolAddress((void**)&p_att, g_att);

    bf16 *hsH,*hsL,*wqaH,*wqaL,*qaH,*qaL,*wqbH,*wqbL,*qH,*qL,*wkvH,*wkvL,*kH,*kL;
    bf16 *vTH,*vTL,*wkcH,*wkcL,*qinH,*qinL,*scH,*scL,*ctxH,*ctxL,*wvcH,*wvcL,*attH,*attL,*woH,*woL;
    cudaGetSymbolAddress((void**)&hsH, g_hsH);   cudaGetSymbolAddress((void**)&hsL, g_hsL);
    cudaGetSymbolAddress((void**)&wqaH, g_wqaT_H); cudaGetSymbolAddress((void**)&wqaL, g_wqaT_L);
    cudaGetSymbolAddress((void**)&qaH, g_qaH);   cudaGetSymbolAddress((void**)&qaL, g_qaL);
    cudaGetSymbolAddress((void**)&wqbH, g_wqbT_H); cudaGetSymbolAddress((void**)&wqbL, g_wqbT_L);
    cudaGetSymbolAddress((void**)&qH, g_qH);     cudaGetSymbolAddress((void**)&qL, g_qL);
    cudaGetSymbolAddress((void**)&wkvH, g_wkvaT_H); cudaGetSymbolAddress((void**)&wkvL, g_wkvaT_L);
    cudaGetSymbolAddress((void**)&kH, g_kH);     cudaGetSymbolAddress((void**)&kL, g_kL);
    cudaGetSymbolAddress((void**)&vTH, g_vT_H);  cudaGetSymbolAddress((void**)&vTL, g_vT_L);
    cudaGetSymbolAddress((void**)&wkcH, g_wkcT_H); cudaGetSymbolAddress((void**)&wkcL, g_wkcT_L);
    cudaGetSymbolAddress((void**)&qinH, g_qinH); cudaGetSymbolAddress((void**)&qinL, g_qinL);
    cudaGetSymbolAddress((void**)&scH, g_scH);   cudaGetSymbolAddress((void**)&scL, g_scL);
    cudaGetSymbolAddress((void**)&ctxH, g_ctxH); cudaGetSymbolAddress((void**)&ctxL, g_ctxL);
    cudaGetSymbolAddress((void**)&wvcH, g_wvcT_H); cudaGetSymbolAddress((void**)&wvcL, g_wvcT_L);
    cudaGetSymbolAddress((void**)&attH, g_attH); cudaGetSymbolAddress((void**)&attL, g_attL);
    cudaGetSymbolAddress((void**)&woH, g_woT_H); cudaGetSymbolAddress((void**)&woL, g_woT_L);

    cudaFuncSetAttribute(gemm3, cudaFuncAttributeMaxDynamicSharedMemorySize, GSM_DYN);
    const int DS = GSM_DYN;
    dim3 tb(32, 8);

    // --- preprocess weights (transpose + split) ---
    tconv<<<dim3(QLRD/32, HIDD/32), tb>>>(w_q_a, wqaH, wqaL, HIDD, QLRD, QLRD, QLRD, 0, 0);
    tconv<<<dim3(QBN/32,  QLRD/32), tb>>>(w_q_b, wqbH, wqbL, QLRD, QBN, QBN, QBN, 0, 0);
    tconv<<<dim3(640/32,  HIDD/32), tb>>>(w_kv_a, wkvH, wkvL, HIDD, DQK, 640, DQK, 0, 0);
    tconv<<<dim3(DLAT/32, NOPED/32, HH), tb>>>(w_kc, wkcH, wkcL, NOPED, DLAT, DLAT, DLAT,
        (long long)NOPED*DLAT, (long long)DLAT*NOPED);
    tconv<<<dim3(NOPED/32, DLAT/32, HH), tb>>>(w_vc, wvcH, wvcL, DLAT, NOPED, NOPED, NOPED,
        (long long)DLAT*NOPED, (long long)NOPED*DLAT);
    tconv<<<dim3(HIDD/32, ATTN/32), tb>>>(w_o, woH, woL, ATTN, HIDD, HIDD, HIDD, 0, 0);

    // --- pipeline ---
    long long n4;
    n4 = (long long)TT*HIDD/4;
    conv_split<<<cblk(n4), 256>>>(hs, hsH, hsL, n4);

    // 1) qa = hs @ w_q_a
    gemm3<<<dim3(QLRD/128, 16, 1), 256, DS>>>(hsH, hsL, wqaH, wqaL, p_qa,
        QLRD, HIDD, HIDD, HIDD, QLRD, 0, 0, 0, 0);
    rmsnorm_rows<<<TT, 256>>>(p_qa, q_a_ln_w, QLRD);
    n4 = (long long)TT*QLRD/4;
    conv_split<<<cblk(n4), 256>>>(p_qa, qaH, qaL, n4);

    // 3) q = qa @ w_q_b
    gemm3<<<dim3(QBN/128, 16, 1), 256, DS>>>(qaH, qaL, wqbH, wqbL, p_q,
        QBN, QLRD, QLRD, QLRD, QBN, 0, 0, 0, 0);

    // 4) latent = hs @ w_kv_a
    gemm3<<<dim3(5, 16, 1), 256, DS>>>(hsH, hsL, wkvH, wkvL, p_lat,
        DQK, HIDD, HIDD, HIDD, DQK, 0, 0, 0, 0);

    // 5) k_input
    build_k<<<TT, 256>>>(p_lat, kv_ln_w, p_k);
    n4 = (long long)TT*DQK/4;
    conv_split<<<cblk(n4), 256>>>(p_k, kH, kL, n4);
    tconv<<<dim3(DLAT/32, TT/32), tb>>>(p_k, vTH, vTL, TT, DLAT, DLAT, DQK, 0, 0);

    // 7) qin nope part per head: q_nope @ w_kc[h]
    n4 = (long long)TT*QBN/4;
    conv_split<<<cblk(n4), 256>>>(p_q, qH, qL, n4);
    gemm3<<<dim3(DLAT/128, 16, HH), 256, DS>>>(qH, qL, wkcH, wkcL, p_qin,
        DLAT, NOPED, QBN, NOPED, HH*DQK,
        (long long)QKDD, (long long)DLAT*NOPED, (long long)DQK, 0);

    // 8) qin rope part
    rope_q<<<dim3(TT, HH), 32>>>(p_q, p_qin);
    n4 = (long long)TT*HH*DQK/4;
    conv_split<<<cblk(n4), 256>>>(p_qin, qinH, qinL, n4);

    // 9) scores (causal-skip)
    gemm3<<<dim3(16, 16, HH), 256, DS>>>(qinH, qinL, kH, kL, p_sc,
        TT, DQK, HH*DQK, DQK, TT,
        (long long)DQK, 0LL, (long long)TT*TT, 1);

    // 10) softmax
    softmax_causal<<<dim3(TT, HH), 256>>>(p_sc);
    n4 = (long long)HH*TT*TT/4;
    conv_split<<<cblk(n4), 256>>>(p_sc, scH, scL, n4);

    // 11) ctx = probs @ v (k-limited)
    gemm3<<<dim3(DLAT/128, 16, HH), 256, DS>>>(scH, scL, vTH, vTL, p_ctx,
        DLAT, TT, TT, TT, DLAT,
        (long long)TT*TT, 0LL, (long long)TT*DLAT, 2);

    // 12) att = ctx @ w_vc per head
    n4 = (long long)HH*TT*DLAT/4;
    conv_split<<<cblk(n4), 256>>>(p_ctx, ctxH, ctxL, n4);
    gemm3<<<dim3(1, 16, HH), 256, DS>>>(ctxH, ctxL, wvcH, wvcL, p_att,
        NOPED, DLAT, DLAT, DLAT, ATTN,
        (long long)TT*DLAT, (long long)NOPED*DLAT, (long long)NOPED, 0);

    // 13) out = att @ w_o
    n4 = (long long)TT*ATTN/4;
    conv_split<<<cblk(n4), 256>>>(p_att, attH, attL, n4);
    gemm3<<<dim3(HIDD/128, 16, 1), 256, DS>>>(attH, attL, woH, woL, out,
        HIDD, ATTN, ATTN, ATTN, HIDD, 0, 0, 0, 0);
}

// round 10
// speedup vs baseline: 3.5403x; 1.3175x over previous
#include <cuda_runtime.h>
#include <cuda_bf16.h>
#include <math.h>
#include <stdint.h>

#define TT     2048
#define HIDD   5120
#define ROPED  64
#define NOPED  128
#define HH     32
#define QKDD   192
#define QLRD   1536
#define DQK    576
#define DLAT   512
#define QBN    6144   // H*QKD
#define ATTN   4096   // H*VDIM
#define SCALE_F 0.07216878364870323f   // 1/sqrt(192)
#define EPS_F  1e-6f

typedef __nv_bfloat16 bf16;

// ----------------------------- f32 scratch -----------------------------------
__device__ float g_qa    [(size_t)TT * QLRD];
__device__ float g_q     [(size_t)TT * QBN];
__device__ float g_lat   [(size_t)TT * DQK];
__device__ float g_k     [(size_t)TT * DQK];
__device__ float g_scores[(size_t)HH * TT * TT];

// --------------------------- bf16 hi/lo scratch -------------------------------
__device__ bf16 g_hsH [(size_t)TT*HIDD],      g_hsL [(size_t)TT*HIDD];
__device__ bf16 g_wqaT_H[(size_t)QLRD*HIDD],  g_wqaT_L[(size_t)QLRD*HIDD];
__device__ bf16 g_qaH [(size_t)TT*QLRD],      g_qaL [(size_t)TT*QLRD];
__device__ bf16 g_wqbT_H[(size_t)QBN*QLRD],   g_wqbT_L[(size_t)QBN*QLRD];
__device__ bf16 g_qH  [(size_t)TT*QBN],       g_qL  [(size_t)TT*QBN];
__device__ bf16 g_wkvaT_H[(size_t)640*HIDD],  g_wkvaT_L[(size_t)640*HIDD];   // padded 576->640
__device__ bf16 g_kH  [(size_t)TT*DQK],       g_kL  [(size_t)TT*DQK];
__device__ bf16 g_vT_H[(size_t)DLAT*TT],      g_vT_L[(size_t)DLAT*TT];
__device__ bf16 g_wkcT_H[(size_t)HH*DLAT*NOPED], g_wkcT_L[(size_t)HH*DLAT*NOPED];
__device__ bf16 g_qinH[(size_t)TT*HH*DQK],    g_qinL[(size_t)TT*HH*DQK];
__device__ bf16 g_scH [(size_t)HH*TT*TT],     g_scL [(size_t)HH*TT*TT];
__device__ bf16 g_ctxH[(size_t)HH*TT*DLAT],   g_ctxL[(size_t)HH*TT*DLAT];
__device__ bf16 g_wvcT_H[(size_t)HH*NOPED*DLAT], g_wvcT_L[(size_t)HH*NOPED*DLAT];
__device__ bf16 g_attH[(size_t)TT*ATTN],      g_attL[(size_t)TT*ATTN];
__device__ bf16 g_woT_H[(size_t)HIDD*ATTN],   g_woT_L[(size_t)HIDD*ATTN];

// ------------------------------ helpers ---------------------------------------
__device__ __forceinline__ uint32_t smem_u32(const void* p) {
    uint32_t a;
    asm("{ .reg .u64 t; cvta.to.shared.u64 t, %1; cvt.u32.u64 %0, t; }" : "=r"(a) : "l"(p));
    return a;
}

#define SWZ(o) ((o) ^ (((o) >> 3) & 0x70))

__device__ __forceinline__ void ldm_x4(uint32_t* r, uint32_t addr) {
    asm volatile("ldmatrix.sync.aligned.m8n8.x4.shared.b16 {%0,%1,%2,%3}, [%4];"
        : "=r"(r[0]), "=r"(r[1]), "=r"(r[2]), "=r"(r[3]) : "r"(addr));
}

__device__ __forceinline__ void mma16816(float* c, const uint32_t* a, const uint32_t* b) {
    asm volatile("mma.sync.aligned.m16n8k16.row.col.f32.bf16.bf16.f32 "
        "{%0,%1,%2,%3}, {%4,%5,%6,%7}, {%8,%9}, {%0,%1,%2,%3};"
        : "+f"(c[0]), "+f"(c[1]), "+f"(c[2]), "+f"(c[3])
        : "r"(a[0]), "r"(a[1]), "r"(a[2]), "r"(a[3]), "r"(b[0]), "r"(b[1]));
}

__device__ __forceinline__ void cpa16(uint32_t dst, const void* src) {
    asm volatile("cp.async.cg.shared.global [%0], [%1], 16;" :: "r"(dst), "l"(src));
}
#define CP_COMMIT() asm volatile("cp.async.commit_group;" ::: "memory")
#define CP_WAIT0()  asm volatile("cp.async.wait_group 0;" ::: "memory")
#define CP_WAIT1()  asm volatile("cp.async.wait_group 1;" ::: "memory")

// ----------------------- warp-MMA 3-term split GEMM ---------------------------
// C[M,N] = A[M,K] * BT[N,K]^T; A/BT bf16 hi/lo, K-contig. 128x128 tile, 2-stage
// cp.async pipeline over K-chunks of 64. Optional outputs: f32 C, bf16 OH/OL.
// mode: 0 none, 1 causal-skip (scores), 2 k-limit (pv)
#define T_A_HI 0
#define T_A_LO 16384
#define T_B_HI 32768
#define T_B_LO 49152
#define STG_SZ 65536
#define GSM_DYN (2*STG_SZ + 1024)

__global__ __launch_bounds__(256)
void gemm3(const bf16* __restrict__ AH, const bf16* __restrict__ AL,
           const bf16* __restrict__ BH, const bf16* __restrict__ BL,
           float* __restrict__ C, bf16* __restrict__ OH, bf16* __restrict__ OL,
           int N, int K, int lda, int ldb, int ldc,
           long long sA, long long sB, long long sC, int mode)
{
    const int bm = blockIdx.y * 128, bn = blockIdx.x * 128;
    if (mode == 1 && bn >= bm + 128) return;
    const int kmax = (mode == 2) ? (bm + 128) : K;
    const int nch  = kmax >> 6;

    AH += (long long)blockIdx.z * sA;  AL += (long long)blockIdx.z * sA;
    BH += (long long)blockIdx.z * sB;  BL += (long long)blockIdx.z * sB;

    extern __shared__ char smraw[];
    char* smem = (char*)(((uintptr_t)smraw + 1023) & ~(uintptr_t)1023);
    const uint32_t sb = smem_u32(smem);

    const int tid  = threadIdx.x;
    const int lane = tid & 31, warp = tid >> 5;
    const int wm = (warp >> 2) * 64;
    const int wn = (warp & 3) * 32;

    float acc[4][4][4];
#pragma unroll
    for (int i = 0; i < 4; i++)
#pragma unroll
        for (int j = 0; j < 4; j++)
#pragma unroll
            for (int q = 0; q < 4; q++) acc[i][j][q] = 0.f;

    const int a_row = (lane & 15);
    const int a_kof = (lane & 16) ? 8 : 0;
    const int b_sel = lane >> 3;
    const int b_row = (lane & 7) + ((b_sel & 2) ? 8 : 0);
    const int b_kof = (b_sel & 1) ? 8 : 0;

    // per-thread load geometry (constant)
    const int l_row = tid >> 3, l_c16 = tid & 7;

    // ---- prologue: stage 0 loads for chunk 0 ----
    {
        const uint32_t st = sb;
#pragma unroll
        for (int it = 0; it < 4; it++) {
            int row = l_row + it * 32;
            uint32_t sw = SWZ((uint32_t)(row * 128 + l_c16 * 16));
            size_t gA = (size_t)(bm + row) * lda + l_c16 * 8;
            size_t gB = (size_t)(bn + row) * ldb + l_c16 * 8;
            cpa16(st + T_A_HI + sw, AH + gA);
            cpa16(st + T_A_LO + sw, AL + gA);
            cpa16(st + T_B_HI + sw, BH + gB);
            cpa16(st + T_B_LO + sw, BL + gB);
        }
        CP_COMMIT();
    }

    for (int c = 0; c < nch; c++) {
        if (c + 1 < nch) {
            const uint32_t st = sb + ((c + 1) & 1) * STG_SZ;
            const int k0 = (c + 1) << 6;
#pragma unroll
            for (int it = 0; it < 4; it++) {
                int row = l_row + it * 32;
                uint32_t sw = SWZ((uint32_t)(row * 128 + l_c16 * 16));
                size_t gA = (size_t)(bm + row) * lda + k0 + l_c16 * 8;
                size_t gB = (size_t)(bn + row) * ldb + k0 + l_c16 * 8;
                cpa16(st + T_A_HI + sw, AH + gA);
                cpa16(st + T_A_LO + sw, AL + gA);
                cpa16(st + T_B_HI + sw, BH + gB);
                cpa16(st + T_B_LO + sw, BL + gB);
            }
            CP_COMMIT();
            CP_WAIT1();
        } else {
            CP_WAIT0();
        }
        __syncthreads();

        const uint32_t st = sb + (c & 1) * STG_SZ;
#pragma unroll
        for (int kk = 0; kk < 64; kk += 16) {
            uint32_t bh[4][2], bl[4][2];
#pragma unroll
            for (int p = 0; p < 2; p++) {
                uint32_t boff = SWZ((uint32_t)((wn + p * 16 + b_row) * 128 + (kk + b_kof) * 2));
                uint32_t r[4];
                ldm_x4(r, st + T_B_HI + boff);
                bh[2*p][0] = r[0]; bh[2*p][1] = r[1]; bh[2*p+1][0] = r[2]; bh[2*p+1][1] = r[3];
                ldm_x4(r, st + T_B_LO + boff);
                bl[2*p][0] = r[0]; bl[2*p][1] = r[1]; bl[2*p+1][0] = r[2]; bl[2*p+1][1] = r[3];
            }
#pragma unroll
            for (int mt = 0; mt < 4; mt++) {
                uint32_t aoff = SWZ((uint32_t)((wm + mt * 16 + a_row) * 128 + (kk + a_kof) * 2));
                uint32_t ah[4], al[4];
                ldm_x4(ah, st + T_A_HI + aoff);
                ldm_x4(al, st + T_A_LO + aoff);
#pragma unroll
                for (int nt = 0; nt < 4; nt++) {
                    mma16816(acc[mt][nt], ah, bh[nt]);
                    mma16816(acc[mt][nt], ah, bl[nt]);
                    mma16816(acc[mt][nt], al, bh[nt]);
                }
            }
        }
        __syncthreads();
    }

    // ---- epilogue: f32 and/or bf16 hi/lo ----
#pragma unroll
    for (int mt = 0; mt < 4; mt++) {
#pragma unroll
        for (int nt = 0; nt < 4; nt++) {
            int r = bm + wm + mt * 16 + (lane >> 2);
            int c = bn + wn + nt * 8 + 2 * (lane & 3);
            if (c >= N) continue;
            float v0 = acc[mt][nt][0], v1 = acc[mt][nt][1];
            float v2 = acc[mt][nt][2], v3 = acc[mt][nt][3];
            if (C) {
                float* Cz = C + (long long)blockIdx.z * sC;
                *(float2*)&Cz[(size_t)r * ldc + c]       = make_float2(v0, v1);
                *(float2*)&Cz[(size_t)(r + 8) * ldc + c] = make_float2(v2, v3);
            }
            if (OH) {
                bf16* Hz = OH + (long long)blockIdx.z * sC;
                bf16* Lz = OL + (long long)blockIdx.z * sC;
                bf16 h0 = __float2bfloat16(v0), h1 = __float2bfloat16(v1);
                bf16 h2 = __float2bfloat16(v2), h3 = __float2bfloat16(v3);
                *(__nv_bfloat162*)&Hz[(size_t)r * ldc + c] = __nv_bfloat162(h0, h1);
                *(__nv_bfloat162*)&Hz[(size_t)(r + 8) * ldc + c] = __nv_bfloat162(h2, h3);
                *(__nv_bfloat162*)&Lz[(size_t)r * ldc + c] =
                    __nv_bfloat162(__float2bfloat16(v0 - __bfloat162float(h0)),
                                   __float2bfloat16(v1 - __bfloat162float(h1)));
                *(__nv_bfloat162*)&Lz[(size_t)(r + 8) * ldc + c] =
                    __nv_bfloat162(__float2bfloat16(v2 - __bfloat162float(h2)),
                                   __float2bfloat16(v3 - __bfloat162float(h3)));
            }
        }
    }
}

// --------------------- elementwise f32 -> bf16 hi/lo ---------------------------
__global__ void conv_split(const float* __restrict__ x, bf16* __restrict__ hi,
                           bf16* __restrict__ lo, long long n4)
{
    long long i = (long long)blockIdx.x * blockDim.x + threadIdx.x;
    long long stride = (long long)gridDim.x * blockDim.x;
    for (; i < n4; i += stride) {
        float4 v = ((const float4*)x)[i];
        bf16 hx = __float2bfloat16(v.x), hy = __float2bfloat16(v.y);
        bf16 hz = __float2bfloat16(v.z), hw = __float2bfloat16(v.w);
        __nv_bfloat162* H = (__nv_bfloat162*)hi;
        __nv_bfloat162* L = (__nv_bfloat162*)lo;
        H[2*i]   = __nv_bfloat162(hx, hy);
        H[2*i+1] = __nv_bfloat162(hz, hw);
        L[2*i]   = __nv_bfloat162(__float2bfloat16(v.x - __bfloat162float(hx)),
                                  __float2bfloat16(v.y - __bfloat162float(hy)));
        L[2*i+1] = __nv_bfloat162(__float2bfloat16(v.z - __bfloat162float(hz)),
                                  __float2bfloat16(v.w - __bfloat162float(hw)));
    }
}

// ------------- transpose + split: src[R][C] f32 (lda) -> dst[CP][R] bf16 -------
__global__ void tconv(const float* __restrict__ src, bf16* __restrict__ dh,
                      bf16* __restrict__ dl, int R, int C, int CP, int lda,
                      long long zs, long long zd)
{
    src += (long long)blockIdx.z * zs;
    dh  += (long long)blockIdx.z * zd;
    dl  += (long long)blockIdx.z * zd;
    __shared__ float t[32][33];
    int c  = blockIdx.x * 32 + threadIdx.x;
    int r0 = blockIdx.y * 32;
#pragma unroll
    for (int i = 0; i < 32; i += 8) {
        int r = r0 + threadIdx.y + i;
        t[threadIdx.y + i][threadIdx.x] = (c < C && r < R) ? src[(size_t)r * lda + c] : 0.f;
    }
    __syncthreads();
    int ro = blockIdx.x * 32;
    int co = r0 + threadIdx.x;
#pragma unroll
    for (int i = 0; i < 32; i += 8) {
        int rr = ro + threadIdx.y + i;
        if (rr < CP && co < R) {
            float v = t[threadIdx.x][threadIdx.y + i];
            bf16 h = __float2bfloat16(v);
            dh[(size_t)rr * R + co] = h;
            dl[(size_t)rr * R + co] = __float2bfloat16(v - __bfloat162float(h));
        }
    }
}

// ------------------------- block reduce helper -------------------------------
__device__ __forceinline__ float blockReduce(float v, bool isMax)
{
    __shared__ float sm[9];
    int lane = threadIdx.x & 31, w = threadIdx.x >> 5;
#pragma unroll
    for (int o = 16; o > 0; o >>= 1) {
        float ov = __shfl_xor_sync(0xffffffffu, v, o);
        v = isMax ? fmaxf(v, ov) : v + ov;
    }
    if (lane == 0) sm[w] = v;
    __syncthreads();
    if (w == 0) {
        int nw = blockDim.x >> 5;
        v = (lane < nw) ? sm[lane] : (isMax ? -INFINITY : 0.f);
#pragma unroll
        for (int o = 4; o > 0; o >>= 1) {
            float ov = __shfl_xor_sync(0xffffffffu, v, o);
            v = isMax ? fmaxf(v, ov) : v + ov;
        }
        if (lane == 0) sm[8] = v;
    }
    __syncthreads();
    return sm[8];
}

// -------------- rmsnorm rows, fused split output (hi/lo bf16) -----------------
__global__ void rmsnorm_split(const float* __restrict__ x, const float* __restrict__ w,
                              bf16* __restrict__ oh, bf16* __restrict__ ol, int n)
{
    const float* row = x + (size_t)blockIdx.x * n;
    bf16* rh = oh + (size_t)blockIdx.x * n;
    bf16* rl = ol + (size_t)blockIdx.x * n;
    float s = 0.f;
    for (int i = threadIdx.x; i < n; i += blockDim.x) { float v = row[i]; s += v * v; }
    s = blockReduce(s, false);
    float sc = rsqrtf(s / (float)n + EPS_F);
    for (int i = threadIdx.x; i < n; i += blockDim.x) {
        float v = row[i] * sc * w[i];
        bf16 h = __float2bfloat16(v);
        rh[i] = h;
        rl[i] = __float2bfloat16(v - __bfloat162float(h));
    }
}

__device__ __forceinline__ void rope_cs(int posv, int j, float& c, float& s)
{
    float e    = (float)(2 * j) * (1.0f / 64.0f);
    float invf = 1.0f / powf(10000.0f, e);
    float freq = (float)posv * invf;
    double fd  = (double)freq;
    double q   = floor(fd * 0.15915494309189535);
    double r   = fd - q * 6.283185307179586;
    float  rf  = (float)r;
    c = cosf(rf); s = sinf(rf);
}

__global__ void build_k(const float* __restrict__ lat, const float* __restrict__ w,
                        float* __restrict__ k)
{
    int t = blockIdx.x;
    const float* L = lat + (size_t)t * DQK;
    float*       K = k   + (size_t)t * DQK;
    float ssq = 0.f;
    for (int i = threadIdx.x; i < DLAT; i += blockDim.x) { float v = L[i]; ssq += v * v; }
    ssq = blockReduce(ssq, false);
    float sc = rsqrtf(ssq / (float)DLAT + EPS_F);
    for (int i = threadIdx.x; i < DLAT; i += blockDim.x) K[i] = L[i] * sc * w[i];
    if (threadIdx.x < 32) {
        int j = threadIdx.x;
        float c, s;
        rope_cs(t, j, c, s);
        float x1 = L[DLAT + 2*j], x2 = L[DLAT + 2*j + 1];
        K[DLAT + 2*j]     = x1 * c - x2 * s;
        K[DLAT + 2*j + 1] = x2 * c + x1 * s;
    }
}

// ------------- q-side rope, writing qin hi/lo bf16 directly ------------------
__global__ void rope_q(const float* __restrict__ q, bf16* __restrict__ qh,
                       bf16* __restrict__ ql)
{
    int t = blockIdx.x, h = blockIdx.y, j = threadIdx.x;
    const float* src = q + (size_t)t * QBN + h * QKDD + NOPED;
    size_t off = ((size_t)t * HH + h) * DQK + DLAT;
    float c, s;
    rope_cs(t, j, c, s);
    float x1 = src[2*j], x2 = src[2*j + 1];
    float o1 = x1 * c - x2 * s;
    float o2 = x2 * c + x1 * s;
    bf16 h1 = __float2bfloat16(o1), h2 = __float2bfloat16(o2);
    qh[off + 2*j]     = h1;
    qh[off + 2*j + 1] = h2;
    ql[off + 2*j]     = __float2bfloat16(o1 - __bfloat162float(h1));
    ql[off + 2*j + 1] = __float2bfloat16(o2 - __bfloat162float(h2));
}

// ------- causal softmax fused with bf16 hi/lo split output -------------------
__global__ void softmax_split(const float* __restrict__ scores,
                              bf16* __restrict__ SH, bf16* __restrict__ SL)
{
    int t = blockIdx.x, h = blockIdx.y;
    const float* row = scores + ((size_t)h * TT + t) * TT;
    bf16* oh = SH + ((size_t)h * TT + t) * TT;
    bf16* ol = SL + ((size_t)h * TT + t) * TT;
    int n = t + 1;
    int nlim = ((t >> 7) + 1) << 7;   // block-aligned extent read by PV gemm

    float m = -INFINITY;
    for (int i = threadIdx.x; i < n; i += blockDim.x)
        m = fmaxf(m, row[i] * SCALE_F);
    m = blockReduce(m, true);

    float s = 0.f;
    for (int i = threadIdx.x; i < n; i += blockDim.x)
        s += expf(row[i] * SCALE_F - m);
    s = blockReduce(s, false);
    float inv = 1.f / s;

    for (int i = threadIdx.x; i < nlim; i += blockDim.x) {
        float p = (i < n) ? expf(row[i] * SCALE_F - m) * inv : 0.f;
        bf16 hp = __float2bfloat16(p);
        oh[i] = hp;
        ol[i] = __float2bfloat16(p - __bfloat162float(hp));
    }
}

// ------------------------------- launch --------------------------------------
static inline int cblk(long long n4) {
    long long b = (n4 + 255) / 256;
    return (int)(b > 262144 ? 262144 : b);
}

extern "C" void kernel_launch(void* const* d_in, const int* in_sizes, int n_in,
                              void* d_out, int out_size)
{
    const float* hs       = (const float*)d_in[0];
    const float* w_q_a    = (const float*)d_in[2];
    const float* q_a_ln_w = (const float*)d_in[3];
    const float* w_q_b    = (const float*)d_in[4];
    const float* w_kv_a   = (const float*)d_in[5];
    const float* kv_ln_w  = (const float*)d_in[6];
    const float* w_kc     = (const float*)d_in[7];
    const float* w_vc     = (const float*)d_in[8];
    const float* w_o      = (const float*)d_in[9];
    float*       out      = (float*)d_out;

    float *p_qa, *p_q, *p_lat, *p_k, *p_sc;
    cudaGetSymbolAddress((void**)&p_qa,  g_qa);
    cudaGetSymbolAddress((void**)&p_q,   g_q);
    cudaGetSymbolAddress((void**)&p_lat, g_lat);
    cudaGetSymbolAddress((void**)&p_k,   g_k);
    cudaGetSymbolAddress((void**)&p_sc,  g_scores);

    bf16 *hsH,*hsL,*wqaH,*wqaL,*qaH,*qaL,*wqbH,*wqbL,*qH,*qL,*wkvH,*wkvL,*kH,*kL;
    bf16 *vTH,*vTL,*wkcH,*wkcL,*qinH,*qinL,*scH,*scL,*ctxH,*ctxL,*wvcH,*wvcL,*attH,*attL,*woH,*woL;
    cudaGetSymbolAddress((void**)&hsH, g_hsH);   cudaGetSymbolAddress((void**)&hsL, g_hsL);
    cudaGetSymbolAddress((void**)&wqaH, g_wqaT_H); cudaGetSymbolAddress((void**)&wqaL, g_wqaT_L);
    cudaGetSymbolAddress((void**)&qaH, g_qaH);   cudaGetSymbolAddress((void**)&qaL, g_qaL);
    cudaGetSymbolAddress((void**)&wqbH, g_wqbT_H); cudaGetSymbolAddress((void**)&wqbL, g_wqbT_L);
    cudaGetSymbolAddress((void**)&qH, g_qH);     cudaGetSymbolAddress((void**)&qL, g_qL);
    cudaGetSymbolAddress((void**)&wkvH, g_wkvaT_H); cudaGetSymbolAddress((void**)&wkvL, g_wkvaT_L);
    cudaGetSymbolAddress((void**)&kH, g_kH);     cudaGetSymbolAddress((void**)&kL, g_kL);
    cudaGetSymbolAddress((void**)&vTH, g_vT_H);  cudaGetSymbolAddress((void**)&vTL, g_vT_L);
    cudaGetSymbolAddress((void**)&wkcH, g_wkcT_H); cudaGetSymbolAddress((void**)&wkcL, g_wkcT_L);
    cudaGetSymbolAddress((void**)&qinH, g_qinH); cudaGetSymbolAddress((void**)&qinL, g_qinL);
    cudaGetSymbolAddress((void**)&scH, g_scH);   cudaGetSymbolAddress((void**)&scL, g_scL);
    cudaGetSymbolAddress((void**)&ctxH, g_ctxH); cudaGetSymbolAddress((void**)&ctxL, g_ctxL);
    cudaGetSymbolAddress((void**)&wvcH, g_wvcT_H); cudaGetSymbolAddress((void**)&wvcL, g_wvcT_L);
    cudaGetSymbolAddress((void**)&attH, g_attH); cudaGetSymbolAddress((void**)&attL, g_attL);
    cudaGetSymbolAddress((void**)&woH, g_woT_H); cudaGetSymbolAddress((void**)&woL, g_woT_L);

    cudaFuncSetAttribute(gemm3, cudaFuncAttributeMaxDynamicSharedMemorySize, GSM_DYN);
    const int DS = GSM_DYN;
    dim3 tb(32, 8);

    // --- preprocess weights (transpose + split) ---
    tconv<<<dim3(QLRD/32, HIDD/32), tb>>>(w_q_a, wqaH, wqaL, HIDD, QLRD, QLRD, QLRD, 0, 0);
    tconv<<<dim3(QBN/32,  QLRD/32), tb>>>(w_q_b, wqbH, wqbL, QLRD, QBN, QBN, QBN, 0, 0);
    tconv<<<dim3(640/32,  HIDD/32), tb>>>(w_kv_a, wkvH, wkvL, HIDD, DQK, 640, DQK, 0, 0);
    tconv<<<dim3(DLAT/32, NOPED/32, HH), tb>>>(w_kc, wkcH, wkcL, NOPED, DLAT, DLAT, DLAT,
        (long long)NOPED*DLAT, (long long)DLAT*NOPED);
    tconv<<<dim3(NOPED/32, DLAT/32, HH), tb>>>(w_vc, wvcH, wvcL, DLAT, NOPED, NOPED, NOPED,
        (long long)DLAT*NOPED, (long long)NOPED*DLAT);
    tconv<<<dim3(HIDD/32, ATTN/32), tb>>>(w_o, woH, woL, ATTN, HIDD, HIDD, HIDD, 0, 0);

    // --- pipeline ---
    long long n4 = (long long)TT*HIDD/4;
    conv_split<<<cblk(n4), 256>>>(hs, hsH, hsL, n4);

    // 1) qa = hs @ w_q_a  (f32 out for rmsnorm)
    gemm3<<<dim3(QLRD/128, 16, 1), 256, DS>>>(hsH, hsL, wqaH, wqaL, p_qa, 0, 0,
        QLRD, HIDD, HIDD, HIDD, QLRD, 0, 0, 0, 0);
    // 2) rmsnorm fused split
    rmsnorm_split<<<TT, 256>>>(p_qa, q_a_ln_w, qaH, qaL, QLRD);

    // 3) q = qa @ w_q_b  (f32 for rope_q + hi/lo for the nope gemm A-operand)
    gemm3<<<dim3(QBN/128, 16, 1), 256, DS>>>(qaH, qaL, wqbH, wqbL, p_q, qH, qL,
        QBN, QLRD, QLRD, QLRD, QBN, 0, 0, 0, 0);

    // 4) latent = hs @ w_kv_a (f32)
    gemm3<<<dim3(5, 16, 1), 256, DS>>>(hsH, hsL, wkvH, wkvL, p_lat, 0, 0,
        DQK, HIDD, HIDD, HIDD, DQK, 0, 0, 0, 0);

    // 5) k_input + splits
    build_k<<<TT, 256>>>(p_lat, kv_ln_w, p_k);
    n4 = (long long)TT*DQK/4;
    conv_split<<<cblk(n4), 256>>>(p_k, kH, kL, n4);
    tconv<<<dim3(DLAT/32, TT/32), tb>>>(p_k, vTH, vTL, TT, DLAT, DLAT, DQK, 0, 0);

    // 7) qin nope = q_nope @ w_kc[h] -> hi/lo direct
    gemm3<<<dim3(DLAT/128, 16, HH), 256, DS>>>(qH, qL, wkcH, wkcL, 0, qinH, qinL,
        DLAT, NOPED, QBN, NOPED, HH*DQK,
        (long long)QKDD, (long long)DLAT*NOPED, (long long)DQK, 0);

    // 8) qin rope part -> hi/lo direct
    rope_q<<<dim3(TT, HH), 32>>>(p_q, qinH, qinL);

    // 9) scores (causal-skip) -> f32
    gemm3<<<dim3(16, 16, HH), 256, DS>>>(qinH, qinL, kH, kL, p_sc, 0, 0,
        TT, DQK, HH*DQK, DQK, TT,
        (long long)DQK, 0LL, (long long)TT*TT, 1);

    // 10) softmax fused split -> scH/scL
    softmax_split<<<dim3(TT, HH), 256>>>(p_sc, scH, scL);

    // 11) ctx = probs @ v (k-limited) -> hi/lo direct
    gemm3<<<dim3(DLAT/128, 16, HH), 256, DS>>>(scH, scL, vTH, vTL, 0, ctxH, ctxL,
        DLAT, TT, TT, TT, DLAT,
        (long long)TT*TT, 0LL, (long long)TT*DLAT, 2);

    // 12) att = ctx @ w_vc[h] -> hi/lo direct
    gemm3<<<dim3(1, 16, HH), 256, DS>>>(ctxH, ctxL, wvcH, wvcL, 0, attH, attL,
        NOPED, DLAT, DLAT, DLAT, ATTN,
        (long long)TT*DLAT, (long long)NOPED*DLAT, (long long)NOPED, 0);

    // 13) out = att @ w_o (f32)
    gemm3<<<dim3(HIDD/128, 16, 1), 256, DS>>>(attH, attL, woH, woL, out, 0, 0,
        HIDD, ATTN, ATTN, ATTN, HIDD, 0, 0, 0, 0);
}